// round 1
// baseline (speedup 1.0000x reference)
#include <cuda_runtime.h>
#include <math.h>

// Problem constants
#define TOK   100352      // 32*56*56 tokens
#define CD    192
#define NWIN  2048        // 32 * 8 * 8 windows
#define NHEAD 6
#define HDIM  32
#define HID   768

// ---------------- scratch (static __device__; no allocations) ----------------
__device__ float g_xw [(size_t)TOK * CD];      // LN1'd, shifted, window-ordered
__device__ float g_qkv[(size_t)TOK * 3 * CD];  // qkv, window-ordered rows
__device__ float g_att[(size_t)TOK * CD];      // attention out, window-ordered
__device__ float g_x2 [(size_t)TOK * CD];      // x + attn (spatial order)
__device__ float g_xn2[(size_t)TOK * CD];      // LN2(x2)
__device__ float g_h  [(size_t)TOK * HID];     // fc1+gelu hidden

// ---------------- LayerNorm (192 threads = 1 token per block) ----------------
// GATHER=true: output row m is window-ordered; source pixel comes from
// shifted spatial position (fuses roll(-3,-3) + window_partition).
template <bool GATHER>
__global__ void ln_kernel(const float* __restrict__ xin,
                          const float* __restrict__ gamma,
                          const float* __restrict__ beta,
                          float* __restrict__ out)
{
    int m = blockIdx.x;
    size_t src;
    if (GATHER) {
        int w = m / 49, n = m - w * 49;
        int bb = w >> 6, rem = w & 63, hb = rem >> 3, wb = rem & 7;
        int r = n / 7, cn = n - r * 7;
        int hh = hb * 7 + r + 3;  if (hh >= 56) hh -= 56;   // roll(-3): read (i+3)%56
        int ww = wb * 7 + cn + 3; if (ww >= 56) ww -= 56;
        src = ((size_t)bb * 3136 + hh * 56 + ww);
    } else {
        src = m;
    }
    int t = threadIdx.x;
    float v = xin[src * CD + t];

    __shared__ float red[2][6];
    float s = v, s2 = v * v;
    #pragma unroll
    for (int o = 16; o > 0; o >>= 1) {
        s  += __shfl_down_sync(0xFFFFFFFFu, s,  o);
        s2 += __shfl_down_sync(0xFFFFFFFFu, s2, o);
    }
    int warp = t >> 5, lane = t & 31;
    if (lane == 0) { red[0][warp] = s; red[1][warp] = s2; }
    __syncthreads();
    if (warp == 0) {
        float a  = (lane < 6) ? red[0][lane] : 0.f;
        float a2 = (lane < 6) ? red[1][lane] : 0.f;
        #pragma unroll
        for (int o = 4; o > 0; o >>= 1) {
            a  += __shfl_down_sync(0xFFFFFFFFu, a,  o);
            a2 += __shfl_down_sync(0xFFFFFFFFu, a2, o);
        }
        if (lane == 0) { red[0][0] = a; red[1][0] = a2; }
    }
    __syncthreads();
    float mean = red[0][0] * (1.f / CD);
    float var  = red[1][0] * (1.f / CD) - mean * mean;
    float inv  = rsqrtf(var + 1e-5f);
    out[(size_t)m * CD + t] = (v - mean) * inv * gamma[t] + beta[t];
}

// ---------------- Tiled SGEMM: C[M,N] = A[M,K] @ B[N,K]^T + bias ------------
// MODE 0: plain (qkv)
// MODE 1: GELU epilogue (fc1)
// MODE 2: + aux[row,col] residual (fc2 -> d_out)
// MODE 3: window-reverse + unshift scatter store, + aux residual (proj)
template <int MODE>
__global__ __launch_bounds__(256)
void gemm_nt(const float* __restrict__ A, const float* __restrict__ B,
             const float* __restrict__ bias, const float* __restrict__ aux,
             float* __restrict__ Cout, int M, int N, int K)
{
    __shared__ float As[16][64];
    __shared__ float Bs[16][64];

    int tid = threadIdx.x;
    int tx = tid & 15, ty = tid >> 4;
    int row0 = blockIdx.y * 64;
    int col0 = blockIdx.x * 64;

    int lr = tid >> 2;          // 0..63 (tile row)
    int lc = (tid & 3) * 4;     // 0,4,8,12 (k offset)
    const float* Ag = A + (size_t)(row0 + lr) * K + lc;
    const float* Bg = B + (size_t)(col0 + lr) * K + lc;

    float acc[4][4];
    #pragma unroll
    for (int i = 0; i < 4; i++)
        #pragma unroll
        for (int j = 0; j < 4; j++) acc[i][j] = 0.f;

    for (int k0 = 0; k0 < K; k0 += 16) {
        float4 av = *(const float4*)(Ag + k0);
        float4 bv = *(const float4*)(Bg + k0);
        As[lc + 0][lr] = av.x; As[lc + 1][lr] = av.y;
        As[lc + 2][lr] = av.z; As[lc + 3][lr] = av.w;
        Bs[lc + 0][lr] = bv.x; Bs[lc + 1][lr] = bv.y;
        Bs[lc + 2][lr] = bv.z; Bs[lc + 3][lr] = bv.w;
        __syncthreads();
        #pragma unroll
        for (int kk = 0; kk < 16; kk++) {
            float a[4], b[4];
            *(float4*)a = *(const float4*)&As[kk][ty * 4];
            *(float4*)b = *(const float4*)&Bs[kk][tx * 4];
            #pragma unroll
            for (int i = 0; i < 4; i++)
                #pragma unroll
                for (int j = 0; j < 4; j++)
                    acc[i][j] += a[i] * b[j];
        }
        __syncthreads();
    }

    #pragma unroll
    for (int i = 0; i < 4; i++) {
        int row = row0 + ty * 4 + i;
        size_t trow = 0;
        if (MODE == 3) {
            int w = row / 49, n = row - w * 49;
            int bb = w >> 6, rem = w & 63, hb = rem >> 3, wb = rem & 7;
            int r = n / 7, cn = n - r * 7;
            int hh = hb * 7 + r + 3;  if (hh >= 56) hh -= 56;   // roll(+3) on write
            int ww = wb * 7 + cn + 3; if (ww >= 56) ww -= 56;
            trow = ((size_t)bb * 3136 + hh * 56 + ww);
        }
        #pragma unroll
        for (int j = 0; j < 4; j++) {
            int col = col0 + tx * 4 + j;
            float v = acc[i][j] + bias[col];
            if (MODE == 0) {
                Cout[(size_t)row * N + col] = v;
            } else if (MODE == 1) {
                v = 0.5f * v * (1.f + erff(v * 0.70710678118654752f));
                Cout[(size_t)row * N + col] = v;
            } else if (MODE == 2) {
                Cout[(size_t)row * N + col] = v + aux[(size_t)row * N + col];
            } else { // MODE 3: scatter + shortcut residual
                Cout[trow * CD + col] = v + aux[trow * CD + col];
            }
        }
    }
}

// ---------------- Attention: one block per (window, head) -------------------
__global__ __launch_bounds__(256)
void attn_kernel(const float* __restrict__ qkv,
                 const float* __restrict__ table,   // (169, 6)
                 const int*   __restrict__ ridx,    // (49*49)
                 float* __restrict__ out)
{
    int w = blockIdx.x / NHEAD;
    int hd = blockIdx.x - w * NHEAD;
    __shared__ float q[49][33], k[49][33], v[49][33];
    __shared__ float S[49][50];

    int tid = threadIdx.x;
    const float* base = qkv + (size_t)w * 49 * (3 * CD) + hd * HDIM;
    for (int i = tid; i < 49 * HDIM; i += 256) {
        int n = i >> 5, d = i & 31;
        const float* rp = base + (size_t)n * (3 * CD);
        q[n][d] = rp[d] * 0.17677669529663687f;   // 1/sqrt(32)
        k[n][d] = rp[CD + d];
        v[n][d] = rp[2 * CD + d];
    }
    __syncthreads();

    for (int i = tid; i < 49 * 49; i += 256) {
        int n = i / 49, m = i - n * 49;
        float s = 0.f;
        #pragma unroll
        for (int d = 0; d < HDIM; d++) s += q[n][d] * k[m][d];
        s += table[ridx[i] * NHEAD + hd];
        S[n][m] = s;
    }
    __syncthreads();

    if (tid < 49) {
        float mx = -1e30f;
        #pragma unroll
        for (int m = 0; m < 49; m++) mx = fmaxf(mx, S[tid][m]);
        float sum = 0.f;
        #pragma unroll
        for (int m = 0; m < 49; m++) {
            float e = __expf(S[tid][m] - mx);
            S[tid][m] = e; sum += e;
        }
        float inv = 1.f / sum;
        #pragma unroll
        for (int m = 0; m < 49; m++) S[tid][m] *= inv;
    }
    __syncthreads();

    float* ob = out + (size_t)w * 49 * CD + hd * HDIM;
    for (int i = tid; i < 49 * HDIM; i += 256) {
        int n = i >> 5, d = i & 31;
        float s = 0.f;
        #pragma unroll
        for (int m = 0; m < 49; m++) s += S[n][m] * v[m][d];
        ob[(size_t)n * CD + d] = s;
    }
}

// ---------------- launch ----------------------------------------------------
extern "C" void kernel_launch(void* const* d_in, const int* in_sizes, int n_in,
                              void* d_out, int out_size)
{
    const float* x    = (const float*)d_in[0];
    const float* n1g  = (const float*)d_in[1];
    const float* n1b  = (const float*)d_in[2];
    const float* qkvw = (const float*)d_in[3];
    const float* qkvb = (const float*)d_in[4];
    const float* pw   = (const float*)d_in[5];
    const float* pb   = (const float*)d_in[6];
    const float* tab  = (const float*)d_in[7];
    const float* n2g  = (const float*)d_in[8];
    const float* n2b  = (const float*)d_in[9];
    const float* f1w  = (const float*)d_in[10];
    const float* f1b  = (const float*)d_in[11];
    const float* f2w  = (const float*)d_in[12];
    const float* f2b  = (const float*)d_in[13];
    const int*   ridx = (const int*)  d_in[14];

    float *p_xw, *p_qkv, *p_att, *p_x2, *p_xn2, *p_h;
    cudaGetSymbolAddress((void**)&p_xw,  g_xw);
    cudaGetSymbolAddress((void**)&p_qkv, g_qkv);
    cudaGetSymbolAddress((void**)&p_att, g_att);
    cudaGetSymbolAddress((void**)&p_x2,  g_x2);
    cudaGetSymbolAddress((void**)&p_xn2, g_xn2);
    cudaGetSymbolAddress((void**)&p_h,   g_h);

    // 1. LN1 + shift + window partition
    ln_kernel<true><<<TOK, CD>>>(x, n1g, n1b, p_xw);
    // 2. QKV GEMM: (100352,192) @ (576,192)^T
    gemm_nt<0><<<dim3(576 / 64, TOK / 64), 256>>>(p_xw, qkvw, qkvb, nullptr, p_qkv, TOK, 576, CD);
    // 3. Windowed attention
    attn_kernel<<<NWIN * NHEAD, 256>>>(p_qkv, tab, ridx, p_att);
    // 4. proj GEMM + window reverse + unshift + residual(x)
    gemm_nt<3><<<dim3(CD / 64, TOK / 64), 256>>>(p_att, pw, pb, x, p_x2, TOK, CD, CD);
    // 5. LN2
    ln_kernel<false><<<TOK, CD>>>(p_x2, n2g, n2b, p_xn2);
    // 6. FC1 + GELU
    gemm_nt<1><<<dim3(HID / 64, TOK / 64), 256>>>(p_xn2, f1w, f1b, nullptr, p_h, TOK, HID, CD);
    // 7. FC2 + residual(x2) -> d_out
    gemm_nt<2><<<dim3(CD / 64, TOK / 64), 256>>>(p_h, f2w, f2b, p_x2, (float*)d_out, TOK, CD, HID);
}

// round 2
// speedup vs baseline: 2.1829x; 2.1829x over previous
#include <cuda_runtime.h>
#include <math.h>
#include <stdint.h>

// Problem constants
#define TOK   100352      // 32*56*56 tokens
#define CD    192
#define NWIN  2048        // 32 * 8 * 8 windows
#define NHEAD 6
#define HDIM  32
#define HID   768

// ---------------- scratch (static __device__; no allocations) ----------------
__device__ float g_xw [(size_t)TOK * CD];      // LN1'd, shifted, window-ordered
__device__ float g_qkv[(size_t)TOK * 3 * CD];  // qkv, window-ordered rows
__device__ float g_att[(size_t)TOK * CD];      // attention out, window-ordered
__device__ float g_x2 [(size_t)TOK * CD];      // x + attn (spatial order)
__device__ float g_xn2[(size_t)TOK * CD];      // LN2(x2)
__device__ float g_h  [(size_t)TOK * HID];     // fc1+gelu hidden

__device__ __forceinline__ uint32_t f2tf32(float f) {
    uint32_t r;
    asm("cvt.rna.tf32.f32 %0, %1;" : "=r"(r) : "f"(f));
    return r;
}

// ---------------- LayerNorm (192 threads = 1 token per block) ----------------
template <bool GATHER>
__global__ void ln_kernel(const float* __restrict__ xin,
                          const float* __restrict__ gamma,
                          const float* __restrict__ beta,
                          float* __restrict__ out)
{
    int m = blockIdx.x;
    size_t src;
    if (GATHER) {
        int w = m / 49, n = m - w * 49;
        int bb = w >> 6, rem = w & 63, hb = rem >> 3, wb = rem & 7;
        int r = n / 7, cn = n - r * 7;
        int hh = hb * 7 + r + 3;  if (hh >= 56) hh -= 56;   // roll(-3): read (i+3)%56
        int ww = wb * 7 + cn + 3; if (ww >= 56) ww -= 56;
        src = ((size_t)bb * 3136 + hh * 56 + ww);
    } else {
        src = m;
    }
    int t = threadIdx.x;
    float v = xin[src * CD + t];

    __shared__ float red[2][6];
    float s = v, s2 = v * v;
    #pragma unroll
    for (int o = 16; o > 0; o >>= 1) {
        s  += __shfl_down_sync(0xFFFFFFFFu, s,  o);
        s2 += __shfl_down_sync(0xFFFFFFFFu, s2, o);
    }
    int warp = t >> 5, lane = t & 31;
    if (lane == 0) { red[0][warp] = s; red[1][warp] = s2; }
    __syncthreads();
    if (warp == 0) {
        float a  = (lane < 6) ? red[0][lane] : 0.f;
        float a2 = (lane < 6) ? red[1][lane] : 0.f;
        #pragma unroll
        for (int o = 4; o > 0; o >>= 1) {
            a  += __shfl_down_sync(0xFFFFFFFFu, a,  o);
            a2 += __shfl_down_sync(0xFFFFFFFFu, a2, o);
        }
        if (lane == 0) { red[0][0] = a; red[1][0] = a2; }
    }
    __syncthreads();
    float mean = red[0][0] * (1.f / CD);
    float var  = red[1][0] * (1.f / CD) - mean * mean;
    float inv  = rsqrtf(var + 1e-5f);
    out[(size_t)m * CD + t] = (v - mean) * inv * gamma[t] + beta[t];
}

// ---------------- TF32 tensor-core GEMM: C = A[M,K] @ B[N,K]^T + bias -------
// Block tile 128x64, BK=32. 8 warps as 4(M) x 2(N); warp tile 32x32.
// mma.sync.aligned.m16n8k8.tf32 — per warp 2(M) x 4(N) mma tiles.
// MODE 0: plain (qkv) | 1: GELU (fc1) | 2: +aux residual (fc2->out)
// MODE 3: window-reverse + unshift scatter + aux residual (proj)
#define BM 128
#define BN 64
#define BK 32
#define LDP 36   // padded smem stride: banks = 4r+c -> conflict-free frags

template <int MODE>
__global__ __launch_bounds__(256)
void gemm_tf32(const float* __restrict__ A, const float* __restrict__ B,
               const float* __restrict__ bias, const float* __restrict__ aux,
               float* __restrict__ Cout, int M, int N, int K)
{
    __shared__ float As[BM * LDP];
    __shared__ float Bs[BN * LDP];

    int tid = threadIdx.x;
    int warp = tid >> 5, lane = tid & 31;
    int warpM = warp & 3;          // 0..3 -> rows warpM*32
    int warpN = warp >> 2;         // 0..1 -> cols warpN*32
    int row0 = blockIdx.y * BM;
    int col0 = blockIdx.x * BN;

    int gr = lane >> 2;            // groupID 0..7
    int gc = lane & 3;             // threadID_in_group 0..3

    float acc[2][4][4];
    #pragma unroll
    for (int mt = 0; mt < 2; mt++)
        #pragma unroll
        for (int nt = 0; nt < 4; nt++)
            #pragma unroll
            for (int i = 0; i < 4; i++) acc[mt][nt][i] = 0.f;

    for (int k0 = 0; k0 < K; k0 += BK) {
        // ---- stage A tile (128 x 32) ----
        #pragma unroll
        for (int i = 0; i < 4; i++) {
            int idx = tid + i * 256;           // 0..1023
            int row = idx >> 3;                // 0..127
            int kq  = (idx & 7) << 2;          // 0,4,..28
            float4 v = *(const float4*)(A + (size_t)(row0 + row) * K + k0 + kq);
            float* p = &As[row * LDP + kq];
            p[0] = __uint_as_float(f2tf32(v.x));
            p[1] = __uint_as_float(f2tf32(v.y));
            p[2] = __uint_as_float(f2tf32(v.z));
            p[3] = __uint_as_float(f2tf32(v.w));
        }
        // ---- stage B tile (64 x 32) ----
        #pragma unroll
        for (int i = 0; i < 2; i++) {
            int idx = tid + i * 256;           // 0..511
            int row = idx >> 3;                // 0..63
            int kq  = (idx & 7) << 2;
            float4 v = *(const float4*)(B + (size_t)(col0 + row) * K + k0 + kq);
            float* p = &Bs[row * LDP + kq];
            p[0] = __uint_as_float(f2tf32(v.x));
            p[1] = __uint_as_float(f2tf32(v.y));
            p[2] = __uint_as_float(f2tf32(v.z));
            p[3] = __uint_as_float(f2tf32(v.w));
        }
        __syncthreads();

        #pragma unroll
        for (int kk = 0; kk < 4; kk++) {
            int k8 = kk * 8;
            uint32_t afr[2][4], bfr[4][2];
            #pragma unroll
            for (int mt = 0; mt < 2; mt++) {
                int base = (warpM * 32 + mt * 16 + gr) * LDP + k8 + gc;
                afr[mt][0] = __float_as_uint(As[base]);
                afr[mt][1] = __float_as_uint(As[base + 8 * LDP]);
                afr[mt][2] = __float_as_uint(As[base + 4]);
                afr[mt][3] = __float_as_uint(As[base + 8 * LDP + 4]);
            }
            #pragma unroll
            for (int nt = 0; nt < 4; nt++) {
                int base = (warpN * 32 + nt * 8 + gr) * LDP + k8 + gc;
                bfr[nt][0] = __float_as_uint(Bs[base]);
                bfr[nt][1] = __float_as_uint(Bs[base + 4]);
            }
            #pragma unroll
            for (int mt = 0; mt < 2; mt++)
                #pragma unroll
                for (int nt = 0; nt < 4; nt++) {
                    float* d = acc[mt][nt];
                    asm volatile(
                        "mma.sync.aligned.m16n8k8.row.col.f32.tf32.tf32.f32 "
                        "{%0,%1,%2,%3}, {%4,%5,%6,%7}, {%8,%9}, {%0,%1,%2,%3};\n"
                        : "+f"(d[0]), "+f"(d[1]), "+f"(d[2]), "+f"(d[3])
                        : "r"(afr[mt][0]), "r"(afr[mt][1]), "r"(afr[mt][2]), "r"(afr[mt][3]),
                          "r"(bfr[nt][0]), "r"(bfr[nt][1]));
                }
        }
        __syncthreads();
    }

    // ---- epilogue ----
    #pragma unroll
    for (int mt = 0; mt < 2; mt++) {
        #pragma unroll
        for (int half = 0; half < 2; half++) {
            int row = row0 + warpM * 32 + mt * 16 + gr + half * 8;
            size_t orow = row;
            if (MODE == 3) {
                int w = row / 49, n = row - w * 49;
                int bb = w >> 6, rem = w & 63, hb = rem >> 3, wb = rem & 7;
                int r = n / 7, cn = n - r * 7;
                int hh = hb * 7 + r + 3;  if (hh >= 56) hh -= 56;   // roll(+3) write
                int ww = wb * 7 + cn + 3; if (ww >= 56) ww -= 56;
                orow = ((size_t)bb * 3136 + hh * 56 + ww);
            }
            #pragma unroll
            for (int nt = 0; nt < 4; nt++) {
                int col = col0 + warpN * 32 + nt * 8 + gc * 2;
                float v0 = acc[mt][nt][half * 2 + 0] + bias[col];
                float v1 = acc[mt][nt][half * 2 + 1] + bias[col + 1];
                if (MODE == 1) {
                    v0 = 0.5f * v0 * (1.f + erff(v0 * 0.70710678118654752f));
                    v1 = 0.5f * v1 * (1.f + erff(v1 * 0.70710678118654752f));
                } else if (MODE == 2) {
                    const float* ap = aux + (size_t)row * N + col;
                    v0 += ap[0]; v1 += ap[1];
                } else if (MODE == 3) {
                    const float* ap = aux + orow * CD + col;
                    v0 += ap[0]; v1 += ap[1];
                }
                float2 o = make_float2(v0, v1);
                if (MODE == 3)
                    *(float2*)(Cout + orow * CD + col) = o;
                else
                    *(float2*)(Cout + (size_t)row * N + col) = o;
            }
        }
    }
}

// ---------------- Attention: one block per (window, head) -------------------
__global__ __launch_bounds__(256)
void attn_kernel(const float* __restrict__ qkv,
                 const float* __restrict__ table,   // (169, 6)
                 const int*   __restrict__ ridx,    // (49*49)
                 float* __restrict__ out)
{
    int w = blockIdx.x / NHEAD;
    int hd = blockIdx.x - w * NHEAD;
    __shared__ float q[49][33], k[49][33], v[49][33];
    __shared__ float S[49][50];

    int tid = threadIdx.x;
    const float* base = qkv + (size_t)w * 49 * (3 * CD) + hd * HDIM;
    for (int i = tid; i < 49 * HDIM; i += 256) {
        int n = i >> 5, d = i & 31;
        const float* rp = base + (size_t)n * (3 * CD);
        q[n][d] = rp[d] * 0.17677669529663687f;   // 1/sqrt(32)
        k[n][d] = rp[CD + d];
        v[n][d] = rp[2 * CD + d];
    }
    __syncthreads();

    for (int i = tid; i < 49 * 49; i += 256) {
        int n = i / 49, m = i - n * 49;
        float s = 0.f;
        #pragma unroll
        for (int d = 0; d < HDIM; d++) s += q[n][d] * k[m][d];
        s += table[ridx[i] * NHEAD + hd];
        S[n][m] = s;
    }
    __syncthreads();

    if (tid < 49) {
        float mx = -1e30f;
        #pragma unroll
        for (int m = 0; m < 49; m++) mx = fmaxf(mx, S[tid][m]);
        float sum = 0.f;
        #pragma unroll
        for (int m = 0; m < 49; m++) {
            float e = __expf(S[tid][m] - mx);
            S[tid][m] = e; sum += e;
        }
        float inv = 1.f / sum;
        #pragma unroll
        for (int m = 0; m < 49; m++) S[tid][m] *= inv;
    }
    __syncthreads();

    float* ob = out + (size_t)w * 49 * CD + hd * HDIM;
    for (int i = tid; i < 49 * HDIM; i += 256) {
        int n = i >> 5, d = i & 31;
        float s = 0.f;
        #pragma unroll
        for (int m = 0; m < 49; m++) s += S[n][m] * v[m][d];
        ob[(size_t)n * CD + d] = s;
    }
}

// ---------------- launch ----------------------------------------------------
extern "C" void kernel_launch(void* const* d_in, const int* in_sizes, int n_in,
                              void* d_out, int out_size)
{
    const float* x    = (const float*)d_in[0];
    const float* n1g  = (const float*)d_in[1];
    const float* n1b  = (const float*)d_in[2];
    const float* qkvw = (const float*)d_in[3];
    const float* qkvb = (const float*)d_in[4];
    const float* pw   = (const float*)d_in[5];
    const float* pb   = (const float*)d_in[6];
    const float* tab  = (const float*)d_in[7];
    const float* n2g  = (const float*)d_in[8];
    const float* n2b  = (const float*)d_in[9];
    const float* f1w  = (const float*)d_in[10];
    const float* f1b  = (const float*)d_in[11];
    const float* f2w  = (const float*)d_in[12];
    const float* f2b  = (const float*)d_in[13];
    const int*   ridx = (const int*)  d_in[14];

    float *p_xw, *p_qkv, *p_att, *p_x2, *p_xn2, *p_h;
    cudaGetSymbolAddress((void**)&p_xw,  g_xw);
    cudaGetSymbolAddress((void**)&p_qkv, g_qkv);
    cudaGetSymbolAddress((void**)&p_att, g_att);
    cudaGetSymbolAddress((void**)&p_x2,  g_x2);
    cudaGetSymbolAddress((void**)&p_xn2, g_xn2);
    cudaGetSymbolAddress((void**)&p_h,   g_h);

    // 1. LN1 + shift + window partition
    ln_kernel<true><<<TOK, CD>>>(x, n1g, n1b, p_xw);
    // 2. QKV GEMM: (100352,192) @ (576,192)^T
    gemm_tf32<0><<<dim3(576 / BN, TOK / BM), 256>>>(p_xw, qkvw, qkvb, nullptr, p_qkv, TOK, 576, CD);
    // 3. Windowed attention
    attn_kernel<<<NWIN * NHEAD, 256>>>(p_qkv, tab, ridx, p_att);
    // 4. proj GEMM + window reverse + unshift + residual(x)
    gemm_tf32<3><<<dim3(CD / BN, TOK / BM), 256>>>(p_att, pw, pb, x, p_x2, TOK, CD, CD);
    // 5. LN2
    ln_kernel<false><<<TOK, CD>>>(p_x2, n2g, n2b, p_xn2);
    // 6. FC1 + GELU
    gemm_tf32<1><<<dim3(HID / BN, TOK / BM), 256>>>(p_xn2, f1w, f1b, nullptr, p_h, TOK, HID, CD);
    // 7. FC2 + residual(x2) -> d_out
    gemm_tf32<2><<<dim3(CD / BN, TOK / BM), 256>>>(p_h, f2w, f2b, p_x2, (float*)d_out, TOK, CD, HID);
}

// round 3
// speedup vs baseline: 3.2088x; 1.4700x over previous
#include <cuda_runtime.h>
#include <cuda_bf16.h>
#include <math.h>
#include <stdint.h>

// Problem constants
#define TOK   100352      // 32*56*56 tokens
#define CD    192
#define NWIN  2048        // 32 * 8 * 8 windows
#define NHEAD 6
#define HDIM  32
#define HID   768

typedef __nv_bfloat16 bf16;

// ---------------- scratch (static __device__; no allocations) ----------------
__device__ bf16  g_xwb [(size_t)TOK * CD];      // LN1'd, shifted, window-ordered
__device__ float g_qkv [(size_t)TOK * 3 * CD];  // qkv fp32 (attention input)
__device__ bf16  g_attb[(size_t)TOK * CD];      // attention out (window-ordered)
__device__ float g_x2  [(size_t)TOK * CD];      // x + attn (spatial order)
__device__ bf16  g_xn2b[(size_t)TOK * CD];      // LN2(x2)
__device__ bf16  g_hb  [(size_t)TOK * HID];     // fc1+gelu hidden
// bf16 weights
__device__ bf16  g_wqkv[576 * CD];
__device__ bf16  g_wp  [CD * CD];
__device__ bf16  g_wf1 [HID * CD];
__device__ bf16  g_wf2 [CD * HID];

__global__ void cvt_kernel(const float* __restrict__ s, bf16* __restrict__ d, int n) {
    int i = blockIdx.x * 256 + threadIdx.x;
    if (i < n) d[i] = __float2bfloat16(s[i]);
}

// ---------------- LayerNorm (192 threads = 1 token per block) ----------------
template <bool GATHER>
__global__ void ln_kernel(const float* __restrict__ xin,
                          const float* __restrict__ gamma,
                          const float* __restrict__ beta,
                          bf16* __restrict__ out)
{
    int m = blockIdx.x;
    size_t src;
    if (GATHER) {
        int w = m / 49, n = m - w * 49;
        int bb = w >> 6, rem = w & 63, hb = rem >> 3, wb = rem & 7;
        int r = n / 7, cn = n - r * 7;
        int hh = hb * 7 + r + 3;  if (hh >= 56) hh -= 56;   // roll(-3)
        int ww = wb * 7 + cn + 3; if (ww >= 56) ww -= 56;
        src = ((size_t)bb * 3136 + hh * 56 + ww);
    } else {
        src = m;
    }
    int t = threadIdx.x;
    float v = xin[src * CD + t];

    __shared__ float red[2][6];
    float s = v, s2 = v * v;
    #pragma unroll
    for (int o = 16; o > 0; o >>= 1) {
        s  += __shfl_down_sync(0xFFFFFFFFu, s,  o);
        s2 += __shfl_down_sync(0xFFFFFFFFu, s2, o);
    }
    int warp = t >> 5, lane = t & 31;
    if (lane == 0) { red[0][warp] = s; red[1][warp] = s2; }
    __syncthreads();
    if (warp == 0) {
        float a  = (lane < 6) ? red[0][lane] : 0.f;
        float a2 = (lane < 6) ? red[1][lane] : 0.f;
        #pragma unroll
        for (int o = 4; o > 0; o >>= 1) {
            a  += __shfl_down_sync(0xFFFFFFFFu, a,  o);
            a2 += __shfl_down_sync(0xFFFFFFFFu, a2, o);
        }
        if (lane == 0) { red[0][0] = a; red[1][0] = a2; }
    }
    __syncthreads();
    float mean = red[0][0] * (1.f / CD);
    float var  = red[1][0] * (1.f / CD) - mean * mean;
    float inv  = rsqrtf(var + 1e-5f);
    out[(size_t)m * CD + t] = __float2bfloat16((v - mean) * inv * gamma[t] + beta[t]);
}

// ---------------- bf16 tensor-core GEMM: C = A[M,K] @ B[N,K]^T + bias -------
// 128x64 block tile, BK=32, double-buffered cp.async, ldmatrix.x4 fragments.
// 8 warps: 4(M) x 2(N); warp tile 32x32; mma.m16n8k16.
// MODE 0: fp32 out (qkv) | 1: GELU -> bf16 (fc1) | 2: +aux -> fp32 (fc2)
// MODE 3: window-reverse + unshift scatter + aux -> fp32 (proj)
#define BM 128
#define BN 64
#define BK 32

__device__ __forceinline__ void cp16(uint32_t dst, const void* src) {
    asm volatile("cp.async.cg.shared.global [%0], [%1], 16;\n" :: "r"(dst), "l"(src));
}
__device__ __forceinline__ void ldsm_x4(uint32_t* r, uint32_t addr) {
    asm volatile("ldmatrix.sync.aligned.m8n8.x4.shared.b16 {%0,%1,%2,%3}, [%4];\n"
                 : "=r"(r[0]), "=r"(r[1]), "=r"(r[2]), "=r"(r[3]) : "r"(addr));
}

template <int MODE, typename OutT>
__global__ __launch_bounds__(256)
void gemm_bf16(const bf16* __restrict__ A, const bf16* __restrict__ B,
               const float* __restrict__ bias, const float* __restrict__ aux,
               OutT* __restrict__ Cout, int M, int N, int K)
{
    __shared__ __align__(16) uint4 As[2][BM * 4];   // 16KB (2 bufs x 8KB)
    __shared__ __align__(16) uint4 Bs[2][BN * 4];   // 8KB

    int tid = threadIdx.x;
    int warp = tid >> 5, lane = tid & 31;
    int warpM = warp & 3;
    int warpN = warp >> 2;
    int row0 = blockIdx.y * BM;
    int col0 = blockIdx.x * BN;

    uint32_t sA = (uint32_t)__cvta_generic_to_shared(&As[0][0]);
    uint32_t sB = (uint32_t)__cvta_generic_to_shared(&Bs[0][0]);

    float acc[2][4][4];
    #pragma unroll
    for (int mt = 0; mt < 2; mt++)
        #pragma unroll
        for (int nt = 0; nt < 4; nt++)
            #pragma unroll
            for (int i = 0; i < 4; i++) acc[mt][nt][i] = 0.f;

    const int nk = K / BK;

    // stage tile 'it' into buffer 'buf'
    auto stage = [&](int buf, int k0) {
        // A: 512 chunks of 16B
        #pragma unroll
        for (int j = 0; j < 2; j++) {
            int idx = tid + j * 256;
            int row = idx >> 2, c = idx & 3;
            int sw = c ^ ((row >> 1) & 3);
            uint32_t dst = sA + (buf * BM * 4 + row * 4 + sw) * 16;
            cp16(dst, A + (size_t)(row0 + row) * K + k0 + c * 8);
        }
        // B: 256 chunks
        {
            int row = tid >> 2, c = tid & 3;
            int sw = c ^ ((row >> 1) & 3);
            uint32_t dst = sB + (buf * BN * 4 + row * 4 + sw) * 16;
            cp16(dst, B + (size_t)(col0 + row) * K + k0 + c * 8);
        }
    };

    stage(0, 0);
    asm volatile("cp.async.commit_group;\n" ::: "memory");

    int buf = 0;
    for (int it = 0; it < nk; it++) {
        asm volatile("cp.async.wait_group 0;\n" ::: "memory");
        __syncthreads();
        if (it + 1 < nk) {
            stage(buf ^ 1, (it + 1) * BK);
            asm volatile("cp.async.commit_group;\n" ::: "memory");
        }
        uint32_t aBase = sA + buf * BM * 4 * 16;
        uint32_t bBase = sB + buf * BN * 4 * 16;
        #pragma unroll
        for (int kk = 0; kk < 2; kk++) {
            uint32_t afr[2][4], bfr[2][4];
            #pragma unroll
            for (int mt = 0; mt < 2; mt++) {
                int r = warpM * 32 + mt * 16 + (lane & 15);
                int c = kk * 2 + (lane >> 4);
                int sw = c ^ ((r >> 1) & 3);
                ldsm_x4(afr[mt], aBase + (r * 4 + sw) * 16);
            }
            #pragma unroll
            for (int np = 0; np < 2; np++) {
                int r = warpN * 32 + np * 16 + ((lane >> 4) << 3) + (lane & 7);
                int c = kk * 2 + ((lane >> 3) & 1);
                int sw = c ^ ((r >> 1) & 3);
                ldsm_x4(bfr[np], bBase + (r * 4 + sw) * 16);
            }
            #pragma unroll
            for (int mt = 0; mt < 2; mt++)
                #pragma unroll
                for (int nt = 0; nt < 4; nt++) {
                    float* d = acc[mt][nt];
                    uint32_t* bb = &bfr[nt >> 1][(nt & 1) * 2];
                    asm volatile(
                        "mma.sync.aligned.m16n8k16.row.col.f32.bf16.bf16.f32 "
                        "{%0,%1,%2,%3}, {%4,%5,%6,%7}, {%8,%9}, {%0,%1,%2,%3};\n"
                        : "+f"(d[0]), "+f"(d[1]), "+f"(d[2]), "+f"(d[3])
                        : "r"(afr[mt][0]), "r"(afr[mt][1]), "r"(afr[mt][2]), "r"(afr[mt][3]),
                          "r"(bb[0]), "r"(bb[1]));
                }
        }
        buf ^= 1;
        __syncthreads();
    }

    // ---- epilogue ----
    int gr = lane >> 2, gc = lane & 3;
    #pragma unroll
    for (int mt = 0; mt < 2; mt++) {
        #pragma unroll
        for (int half = 0; half < 2; half++) {
            int row = row0 + warpM * 32 + mt * 16 + gr + half * 8;
            size_t orow = row;
            if (MODE == 3) {
                int w = row / 49, n = row - w * 49;
                int bb = w >> 6, rem = w & 63, hb = rem >> 3, wb = rem & 7;
                int r = n / 7, cn = n - r * 7;
                int hh = hb * 7 + r + 3;  if (hh >= 56) hh -= 56;   // roll(+3) write
                int ww = wb * 7 + cn + 3; if (ww >= 56) ww -= 56;
                orow = ((size_t)bb * 3136 + hh * 56 + ww);
            }
            #pragma unroll
            for (int nt = 0; nt < 4; nt++) {
                int col = col0 + warpN * 32 + nt * 8 + gc * 2;
                float v0 = acc[mt][nt][half * 2 + 0] + bias[col];
                float v1 = acc[mt][nt][half * 2 + 1] + bias[col + 1];
                if (MODE == 1) {
                    v0 = 0.5f * v0 * (1.f + erff(v0 * 0.70710678118654752f));
                    v1 = 0.5f * v1 * (1.f + erff(v1 * 0.70710678118654752f));
                } else if (MODE == 2) {
                    const float* ap = aux + (size_t)row * N + col;
                    v0 += ap[0]; v1 += ap[1];
                } else if (MODE == 3) {
                    const float* ap = aux + orow * CD + col;
                    v0 += ap[0]; v1 += ap[1];
                }
                if (MODE == 1) {
                    __nv_bfloat162 o = __floats2bfloat162_rn(v0, v1);
                    *(__nv_bfloat162*)((bf16*)Cout + (size_t)row * N + col) = o;
                } else if (MODE == 3) {
                    *(float2*)((float*)Cout + orow * CD + col) = make_float2(v0, v1);
                } else {
                    *(float2*)((float*)Cout + (size_t)row * N + col) = make_float2(v0, v1);
                }
            }
        }
    }
}

// ---------------- Attention: one block per (window, head) -------------------
__global__ __launch_bounds__(256)
void attn_kernel(const float* __restrict__ qkv,
                 const float* __restrict__ table,   // (169, 6)
                 const int*   __restrict__ ridx,    // (49*49)
                 bf16* __restrict__ out)
{
    int w = blockIdx.x / NHEAD;
    int hd = blockIdx.x - w * NHEAD;
    __shared__ float q[49][33], k[49][33], v[49][33];
    __shared__ float S[49][50];

    int tid = threadIdx.x;
    const float* base = qkv + (size_t)w * 49 * (3 * CD) + hd * HDIM;
    for (int i = tid; i < 49 * HDIM; i += 256) {
        int n = i >> 5, d = i & 31;
        const float* rp = base + (size_t)n * (3 * CD);
        q[n][d] = rp[d] * 0.17677669529663687f;   // 1/sqrt(32)
        k[n][d] = rp[CD + d];
        v[n][d] = rp[2 * CD + d];
    }
    __syncthreads();

    for (int i = tid; i < 49 * 49; i += 256) {
        int n = i / 49, m = i - n * 49;
        float s = 0.f;
        #pragma unroll
        for (int d = 0; d < HDIM; d++) s += q[n][d] * k[m][d];
        s += table[ridx[i] * NHEAD + hd];
        S[n][m] = s;
    }
    __syncthreads();

    if (tid < 49) {
        float mx = -1e30f;
        #pragma unroll
        for (int m = 0; m < 49; m++) mx = fmaxf(mx, S[tid][m]);
        float sum = 0.f;
        #pragma unroll
        for (int m = 0; m < 49; m++) {
            float e = __expf(S[tid][m] - mx);
            S[tid][m] = e; sum += e;
        }
        float inv = 1.f / sum;
        #pragma unroll
        for (int m = 0; m < 49; m++) S[tid][m] *= inv;
    }
    __syncthreads();

    bf16* ob = out + (size_t)w * 49 * CD + hd * HDIM;
    for (int i = tid; i < 49 * HDIM; i += 256) {
        int n = i >> 5, d = i & 31;
        float s = 0.f;
        #pragma unroll
        for (int m = 0; m < 49; m++) s += S[n][m] * v[m][d];
        ob[(size_t)n * CD + d] = __float2bfloat16(s);
    }
}

// ---------------- launch ----------------------------------------------------
extern "C" void kernel_launch(void* const* d_in, const int* in_sizes, int n_in,
                              void* d_out, int out_size)
{
    const float* x    = (const float*)d_in[0];
    const float* n1g  = (const float*)d_in[1];
    const float* n1b  = (const float*)d_in[2];
    const float* qkvw = (const float*)d_in[3];
    const float* qkvb = (const float*)d_in[4];
    const float* pw   = (const float*)d_in[5];
    const float* pb   = (const float*)d_in[6];
    const float* tab  = (const float*)d_in[7];
    const float* n2g  = (const float*)d_in[8];
    const float* n2b  = (const float*)d_in[9];
    const float* f1w  = (const float*)d_in[10];
    const float* f1b  = (const float*)d_in[11];
    const float* f2w  = (const float*)d_in[12];
    const float* f2b  = (const float*)d_in[13];
    const int*   ridx = (const int*)  d_in[14];

    bf16 *p_xwb, *p_attb, *p_xn2b, *p_hb, *p_wqkv, *p_wp, *p_wf1, *p_wf2;
    float *p_qkv, *p_x2;
    cudaGetSymbolAddress((void**)&p_xwb,  g_xwb);
    cudaGetSymbolAddress((void**)&p_qkv,  g_qkv);
    cudaGetSymbolAddress((void**)&p_attb, g_attb);
    cudaGetSymbolAddress((void**)&p_x2,   g_x2);
    cudaGetSymbolAddress((void**)&p_xn2b, g_xn2b);
    cudaGetSymbolAddress((void**)&p_hb,   g_hb);
    cudaGetSymbolAddress((void**)&p_wqkv, g_wqkv);
    cudaGetSymbolAddress((void**)&p_wp,   g_wp);
    cudaGetSymbolAddress((void**)&p_wf1,  g_wf1);
    cudaGetSymbolAddress((void**)&p_wf2,  g_wf2);

    // 0. weight conversion to bf16
    cvt_kernel<<<(576 * CD + 255) / 256, 256>>>(qkvw, p_wqkv, 576 * CD);
    cvt_kernel<<<(CD * CD + 255) / 256, 256>>>(pw, p_wp, CD * CD);
    cvt_kernel<<<(HID * CD + 255) / 256, 256>>>(f1w, p_wf1, HID * CD);
    cvt_kernel<<<(CD * HID + 255) / 256, 256>>>(f2w, p_wf2, CD * HID);

    // 1. LN1 + shift + window partition -> bf16
    ln_kernel<true><<<TOK, CD>>>(x, n1g, n1b, p_xwb);
    // 2. QKV GEMM -> fp32
    gemm_bf16<0, float><<<dim3(576 / BN, TOK / BM), 256>>>(p_xwb, p_wqkv, qkvb, nullptr, p_qkv, TOK, 576, CD);
    // 3. Windowed attention -> bf16
    attn_kernel<<<NWIN * NHEAD, 256>>>(p_qkv, tab, ridx, p_attb);
    // 4. proj GEMM + window reverse + unshift + residual(x) -> fp32 x2
    gemm_bf16<3, float><<<dim3(CD / BN, TOK / BM), 256>>>(p_attb, p_wp, pb, x, p_x2, TOK, CD, CD);
    // 5. LN2 -> bf16
    ln_kernel<false><<<TOK, CD>>>(p_x2, n2g, n2b, p_xn2b);
    // 6. FC1 + GELU -> bf16
    gemm_bf16<1, bf16><<<dim3(HID / BN, TOK / BM), 256>>>(p_xn2b, p_wf1, f1b, nullptr, p_hb, TOK, HID, CD);
    // 7. FC2 + residual(x2) -> d_out fp32
    gemm_bf16<2, float><<<dim3(CD / BN, TOK / BM), 256>>>(p_hb, p_wf2, f2b, p_x2, (float*)d_out, TOK, CD, HID);
}

// round 4
// speedup vs baseline: 5.9317x; 1.8486x over previous
#include <cuda_runtime.h>
#include <cuda_bf16.h>
#include <math.h>
#include <stdint.h>

#define TOK   100352
#define CD    192
#define NWIN  2048
#define NHEAD 6
#define HDIM  32
#define HID   768

typedef __nv_bfloat16 bf16;

// ---------------- scratch ----------------------------------------------------
__device__ bf16  g_xwb [(size_t)TOK * CD];
__device__ bf16  g_qkvb[(size_t)TOK * 3 * CD];
__device__ bf16  g_attb[(size_t)TOK * CD];
__device__ float g_x2  [(size_t)TOK * CD];
__device__ bf16  g_xn2b[(size_t)TOK * CD];
__device__ bf16  g_hb  [(size_t)TOK * HID];
__device__ bf16  g_wqkv[576 * CD];
__device__ bf16  g_wp  [CD * CD];
__device__ bf16  g_wf1 [HID * CD];
__device__ bf16  g_wf2 [CD * HID];
__device__ float g_bias6[NHEAD * 49 * 49];

// ---------------- fused convert + bias expand -------------------------------
#define N_QKVW (576 * CD)
#define N_PW   (CD * CD)
#define N_F1W  (HID * CD)
#define N_F2W  (CD * HID)
#define N_WTOT (N_QKVW + N_PW + N_F1W + N_F2W)
#define N_BIAS (NHEAD * 49 * 49)

__global__ void prep_kernel(const float* __restrict__ qkvw, const float* __restrict__ pw,
                            const float* __restrict__ f1w, const float* __restrict__ f2w,
                            const float* __restrict__ tab, const int* __restrict__ ridx)
{
    int i = blockIdx.x * 256 + threadIdx.x;
    if (i < N_QKVW) { g_wqkv[i] = __float2bfloat16(qkvw[i]); return; }
    i -= N_QKVW;
    if (i < N_PW)   { g_wp[i]   = __float2bfloat16(pw[i]);   return; }
    i -= N_PW;
    if (i < N_F1W)  { g_wf1[i]  = __float2bfloat16(f1w[i]);  return; }
    i -= N_F1W;
    if (i < N_F2W)  { g_wf2[i]  = __float2bfloat16(f2w[i]);  return; }
    i -= N_F2W;
    if (i < N_BIAS) {
        int h = i / 2401, nm = i - h * 2401;
        g_bias6[i] = tab[ridx[nm] * NHEAD + h];
    }
}

// ---------------- LayerNorm: one warp per token ------------------------------
template <bool GATHER>
__global__ __launch_bounds__(256)
void ln_warp(const float* __restrict__ xin,
             const float* __restrict__ gamma,
             const float* __restrict__ beta,
             bf16* __restrict__ out)
{
    int m = blockIdx.x * 8 + (threadIdx.x >> 5);
    int lane = threadIdx.x & 31;
    size_t src;
    if (GATHER) {
        int w = m / 49, n = m - w * 49;
        int bb = w >> 6, rem = w & 63, hb = rem >> 3, wb = rem & 7;
        int r = n / 7, cn = n - r * 7;
        int hh = hb * 7 + r + 3;  if (hh >= 56) hh -= 56;
        int ww = wb * 7 + cn + 3; if (ww >= 56) ww -= 56;
        src = ((size_t)bb * 3136 + hh * 56 + ww);
    } else {
        src = m;
    }
    const float* p = xin + src * CD;
    float v[6];
    float s = 0.f, s2 = 0.f;
    #pragma unroll
    for (int i = 0; i < 6; i++) {
        v[i] = p[lane + 32 * i];
        s += v[i]; s2 += v[i] * v[i];
    }
    #pragma unroll
    for (int o = 16; o > 0; o >>= 1) {
        s  += __shfl_xor_sync(0xFFFFFFFFu, s,  o);
        s2 += __shfl_xor_sync(0xFFFFFFFFu, s2, o);
    }
    float mean = s * (1.f / CD);
    float var  = s2 * (1.f / CD) - mean * mean;
    float inv  = rsqrtf(var + 1e-5f);
    bf16* o = out + (size_t)m * CD;
    #pragma unroll
    for (int i = 0; i < 6; i++) {
        int c = lane + 32 * i;
        o[c] = __float2bfloat16((v[i] - mean) * inv * gamma[c] + beta[c]);
    }
}

// ---------------- helpers ----------------------------------------------------
__device__ __forceinline__ void cp16(uint32_t dst, const void* src) {
    asm volatile("cp.async.cg.shared.global [%0], [%1], 16;\n" :: "r"(dst), "l"(src));
}
__device__ __forceinline__ void cp16z(uint32_t dst, const void* src, int sz) {
    asm volatile("cp.async.cg.shared.global [%0], [%1], 16, %2;\n" :: "r"(dst), "l"(src), "r"(sz));
}
__device__ __forceinline__ void ldsm_x4(uint32_t* r, uint32_t addr) {
    asm volatile("ldmatrix.sync.aligned.m8n8.x4.shared.b16 {%0,%1,%2,%3}, [%4];\n"
                 : "=r"(r[0]), "=r"(r[1]), "=r"(r[2]), "=r"(r[3]) : "r"(addr));
}
__device__ __forceinline__ void ldsm_x4t(uint32_t* r, uint32_t addr) {
    asm volatile("ldmatrix.sync.aligned.m8n8.x4.trans.shared.b16 {%0,%1,%2,%3}, [%4];\n"
                 : "=r"(r[0]), "=r"(r[1]), "=r"(r[2]), "=r"(r[3]) : "r"(addr));
}
__device__ __forceinline__ void mma16816(float* d, const uint32_t* a, const uint32_t* b) {
    asm volatile(
        "mma.sync.aligned.m16n8k16.row.col.f32.bf16.bf16.f32 "
        "{%0,%1,%2,%3}, {%4,%5,%6,%7}, {%8,%9}, {%0,%1,%2,%3};\n"
        : "+f"(d[0]), "+f"(d[1]), "+f"(d[2]), "+f"(d[3])
        : "r"(a[0]), "r"(a[1]), "r"(a[2]), "r"(a[3]), "r"(b[0]), "r"(b[1]));
}
__device__ __forceinline__ uint32_t packbf(float a, float b) {
    __nv_bfloat162 t = __floats2bfloat162_rn(a, b);
    return *(uint32_t*)&t;
}

// ---------------- bf16 GEMM (3-stage): C = A[M,K] @ B[N,K]^T + bias ---------
#define BM 128
#define BN 64
#define BK 32
#define NSTG 3

template <int MODE, typename OutT>
__global__ __launch_bounds__(256)
void gemm_bf16(const bf16* __restrict__ A, const bf16* __restrict__ B,
               const float* __restrict__ bias, const float* __restrict__ aux,
               OutT* __restrict__ Cout, int M, int N, int K)
{
    __shared__ __align__(16) uint4 As[NSTG][BM * 4];
    __shared__ __align__(16) uint4 Bs[NSTG][BN * 4];

    int tid = threadIdx.x;
    int warp = tid >> 5, lane = tid & 31;
    int warpM = warp & 3;
    int warpN = warp >> 2;
    int row0 = blockIdx.y * BM;
    int col0 = blockIdx.x * BN;

    uint32_t sA = (uint32_t)__cvta_generic_to_shared(&As[0][0]);
    uint32_t sB = (uint32_t)__cvta_generic_to_shared(&Bs[0][0]);

    float acc[2][4][4];
    #pragma unroll
    for (int mt = 0; mt < 2; mt++)
        #pragma unroll
        for (int nt = 0; nt < 4; nt++)
            #pragma unroll
            for (int i = 0; i < 4; i++) acc[mt][nt][i] = 0.f;

    const int nk = K / BK;

    auto stage = [&](int buf, int k0) {
        #pragma unroll
        for (int j = 0; j < 2; j++) {
            int idx = tid + j * 256;
            int row = idx >> 2, c = idx & 3;
            int sw = c ^ ((row >> 1) & 3);
            cp16(sA + (buf * BM * 4 + row * 4 + sw) * 16,
                 A + (size_t)(row0 + row) * K + k0 + c * 8);
        }
        {
            int row = tid >> 2, c = tid & 3;
            int sw = c ^ ((row >> 1) & 3);
            cp16(sB + (buf * BN * 4 + row * 4 + sw) * 16,
                 B + (size_t)(col0 + row) * K + k0 + c * 8);
        }
    };

    stage(0, 0);
    asm volatile("cp.async.commit_group;\n" ::: "memory");
    if (nk > 1) stage(1, BK);
    asm volatile("cp.async.commit_group;\n" ::: "memory");

    for (int it = 0; it < nk; it++) {
        if (it + 2 < nk) {
            stage((it + 2) % NSTG, (it + 2) * BK);
            asm volatile("cp.async.commit_group;\n" ::: "memory");
        }
        asm volatile("cp.async.wait_group 2;\n" ::: "memory");
        __syncthreads();
        int buf = it % NSTG;
        uint32_t aBase = sA + buf * BM * 4 * 16;
        uint32_t bBase = sB + buf * BN * 4 * 16;
        #pragma unroll
        for (int kk = 0; kk < 2; kk++) {
            uint32_t afr[2][4], bfr[2][4];
            #pragma unroll
            for (int mt = 0; mt < 2; mt++) {
                int r = warpM * 32 + mt * 16 + (lane & 15);
                int c = kk * 2 + (lane >> 4);
                int sw = c ^ ((r >> 1) & 3);
                ldsm_x4(afr[mt], aBase + (r * 4 + sw) * 16);
            }
            #pragma unroll
            for (int np = 0; np < 2; np++) {
                int r = warpN * 32 + np * 16 + ((lane >> 4) << 3) + (lane & 7);
                int c = kk * 2 + ((lane >> 3) & 1);
                int sw = c ^ ((r >> 1) & 3);
                ldsm_x4(bfr[np], bBase + (r * 4 + sw) * 16);
            }
            #pragma unroll
            for (int mt = 0; mt < 2; mt++)
                #pragma unroll
                for (int nt = 0; nt < 4; nt++)
                    mma16816(acc[mt][nt], afr[mt], &bfr[nt >> 1][(nt & 1) * 2]);
        }
        __syncthreads();
    }

    // ---- epilogue ----
    int gr = lane >> 2, gc = lane & 3;
    #pragma unroll
    for (int mt = 0; mt < 2; mt++) {
        #pragma unroll
        for (int half = 0; half < 2; half++) {
            int row = row0 + warpM * 32 + mt * 16 + gr + half * 8;
            size_t orow = row;
            if (MODE == 3) {
                int w = row / 49, n = row - w * 49;
                int bb = w >> 6, rem = w & 63, hb = rem >> 3, wb = rem & 7;
                int r = n / 7, cn = n - r * 7;
                int hh = hb * 7 + r + 3;  if (hh >= 56) hh -= 56;
                int ww = wb * 7 + cn + 3; if (ww >= 56) ww -= 56;
                orow = ((size_t)bb * 3136 + hh * 56 + ww);
            }
            #pragma unroll
            for (int nt = 0; nt < 4; nt++) {
                int col = col0 + warpN * 32 + nt * 8 + gc * 2;
                float v0 = acc[mt][nt][half * 2 + 0] + bias[col];
                float v1 = acc[mt][nt][half * 2 + 1] + bias[col + 1];
                if (MODE == 1) {
                    v0 = 0.5f * v0 * (1.f + erff(v0 * 0.70710678118654752f));
                    v1 = 0.5f * v1 * (1.f + erff(v1 * 0.70710678118654752f));
                } else if (MODE == 2) {
                    const float* ap = aux + (size_t)row * N + col;
                    v0 += ap[0]; v1 += ap[1];
                } else if (MODE == 3) {
                    const float* ap = aux + orow * CD + col;
                    v0 += ap[0]; v1 += ap[1];
                }
                if (sizeof(OutT) == 2) {
                    __nv_bfloat162 o = __floats2bfloat162_rn(v0, v1);
                    *(__nv_bfloat162*)((bf16*)Cout + (size_t)row * N + col) = o;
                } else if (MODE == 3) {
                    *(float2*)((float*)Cout + orow * CD + col) = make_float2(v0, v1);
                } else {
                    *(float2*)((float*)Cout + (size_t)row * N + col) = make_float2(v0, v1);
                }
            }
        }
    }
}

// ---------------- MMA attention: block = (window, head pair) ----------------
// 8 warps: warpgroup 0 -> head 2p, warpgroup 1 -> head 2p+1.
// Padded 64x64x32 S-GEMM, register softmax, FA2 P-repack, PV with ldsm.trans.
__global__ __launch_bounds__(256)
void attn_mma(const bf16* __restrict__ qkv,      // [TOK][576] window-ordered
              const float* __restrict__ bias6,   // [6][49][49]
              bf16* __restrict__ out)            // [TOK][192]
{
    int win = blockIdx.y;
    int hp  = blockIdx.x;
    int tid = threadIdx.x;
    int wg  = tid >> 7;
    int h   = hp * 2 + wg;
    int wgtid = tid & 127;
    int warp  = wgtid >> 5;
    int lane  = tid & 31;

    __shared__ __align__(16) bf16 Qs[2][64 * 32];
    __shared__ __align__(16) bf16 Ks[2][64 * 32];
    __shared__ __align__(16) bf16 Vs[2][64 * 32];

    uint32_t qb = (uint32_t)__cvta_generic_to_shared(&Qs[wg][0]);
    uint32_t kb = (uint32_t)__cvta_generic_to_shared(&Ks[wg][0]);
    uint32_t vb = (uint32_t)__cvta_generic_to_shared(&Vs[wg][0]);

    const bf16* src = qkv + (size_t)win * 49 * 576 + h * HDIM;
    for (int i = wgtid; i < 256; i += 128) {
        int row = i >> 2, c = i & 3;
        int sw = c ^ ((row >> 1) & 3);
        int sz = (row < 49) ? 16 : 0;
        const bf16* s = (row < 49) ? (src + (size_t)row * 576 + c * 8) : src;
        cp16z(qb + (row * 4 + sw) * 16, s, sz);
        cp16z(kb + (row * 4 + sw) * 16, s + CD, sz);
        cp16z(vb + (row * 4 + sw) * 16, s + 2 * CD, sz);
    }
    asm volatile("cp.async.commit_group;\n" ::: "memory");
    asm volatile("cp.async.wait_group 0;\n" ::: "memory");
    __syncthreads();

    // ---- S = Q @ K^T : warp rows 16*warp .. +15, cols 0..63 ----
    float sacc[8][4];
    #pragma unroll
    for (int t = 0; t < 8; t++)
        #pragma unroll
        for (int i = 0; i < 4; i++) sacc[t][i] = 0.f;

    #pragma unroll
    for (int kk = 0; kk < 2; kk++) {
        uint32_t afr[4], bfr[4][4];
        {
            int r = warp * 16 + (lane & 15);
            int c = kk * 2 + (lane >> 4);
            int sw = c ^ ((r >> 1) & 3);
            ldsm_x4(afr, qb + (r * 4 + sw) * 16);
        }
        #pragma unroll
        for (int nb = 0; nb < 4; nb++) {
            int r = nb * 16 + ((lane >> 4) << 3) + (lane & 7);
            int c = kk * 2 + ((lane >> 3) & 1);
            int sw = c ^ ((r >> 1) & 3);
            ldsm_x4(bfr[nb], kb + (r * 4 + sw) * 16);
        }
        #pragma unroll
        for (int nt = 0; nt < 8; nt++)
            mma16816(sacc[nt], afr, &bfr[nt >> 1][(nt & 1) * 2]);
    }

    // ---- scale + bias + mask + softmax (in registers) ----
    const float scale = 0.17677669529663687f;   // 1/sqrt(32)
    int gr = lane >> 2, gc2 = (lane & 3) * 2;
    int rbase = warp * 16 + gr;
    float mx[2] = {-1e30f, -1e30f}, sum[2] = {0.f, 0.f}, inv[2];

    #pragma unroll
    for (int half = 0; half < 2; half++) {
        int row = rbase + half * 8;
        const float* bp = bias6 + ((size_t)h * 49 + row) * 49;
        #pragma unroll
        for (int nt = 0; nt < 8; nt++) {
            #pragma unroll
            for (int j = 0; j < 2; j++) {
                int col = nt * 8 + gc2 + j;
                float v = sacc[nt][half * 2 + j] * scale;
                v = (col < 49 && row < 49) ? (v + bp[col]) : -1e30f;
                sacc[nt][half * 2 + j] = v;
                mx[half] = fmaxf(mx[half], v);
            }
        }
        mx[half] = fmaxf(mx[half], __shfl_xor_sync(0xFFFFFFFFu, mx[half], 1));
        mx[half] = fmaxf(mx[half], __shfl_xor_sync(0xFFFFFFFFu, mx[half], 2));
        #pragma unroll
        for (int nt = 0; nt < 8; nt++) {
            #pragma unroll
            for (int j = 0; j < 2; j++) {
                float e = __expf(sacc[nt][half * 2 + j] - mx[half]);
                sacc[nt][half * 2 + j] = e;
                sum[half] += e;
            }
        }
        sum[half] += __shfl_xor_sync(0xFFFFFFFFu, sum[half], 1);
        sum[half] += __shfl_xor_sync(0xFFFFFFFFu, sum[half], 2);
        inv[half] = 1.f / sum[half];
    }

    // ---- P repack to bf16 A-fragments ----
    uint32_t pfr[4][4];
    #pragma unroll
    for (int ks = 0; ks < 4; ks++) {
        int t0 = 2 * ks, t1 = t0 + 1;
        pfr[ks][0] = packbf(sacc[t0][0], sacc[t0][1]);
        pfr[ks][1] = packbf(sacc[t0][2], sacc[t0][3]);
        pfr[ks][2] = packbf(sacc[t1][0], sacc[t1][1]);
        pfr[ks][3] = packbf(sacc[t1][2], sacc[t1][3]);
    }

    // ---- O = P @ V ----
    float oacc[4][4];
    #pragma unroll
    for (int t = 0; t < 4; t++)
        #pragma unroll
        for (int i = 0; i < 4; i++) oacc[t][i] = 0.f;

    #pragma unroll
    for (int ks = 0; ks < 4; ks++) {
        uint32_t vfr[2][4];
        #pragma unroll
        for (int nb = 0; nb < 2; nb++) {
            int r = ks * 16 + ((lane >> 3) & 1) * 8 + (lane & 7);
            int c = nb * 2 + (lane >> 4);
            int sw = c ^ ((r >> 1) & 3);
            ldsm_x4t(vfr[nb], vb + (r * 4 + sw) * 16);
        }
        #pragma unroll
        for (int nt = 0; nt < 4; nt++)
            mma16816(oacc[nt], pfr[ks], &vfr[nt >> 1][(nt & 1) * 2]);
    }

    // ---- store ----
    bf16* ob = out + (size_t)win * 49 * CD + h * HDIM;
    #pragma unroll
    for (int half = 0; half < 2; half++) {
        int row = rbase + half * 8;
        if (row < 49) {
            #pragma unroll
            for (int nt = 0; nt < 4; nt++) {
                int col = nt * 8 + gc2;
                __nv_bfloat162 o = __floats2bfloat162_rn(oacc[nt][half * 2] * inv[half],
                                                         oacc[nt][half * 2 + 1] * inv[half]);
                *(__nv_bfloat162*)(ob + (size_t)row * CD + col) = o;
            }
        }
    }
}

// ---------------- launch ----------------------------------------------------
extern "C" void kernel_launch(void* const* d_in, const int* in_sizes, int n_in,
                              void* d_out, int out_size)
{
    const float* x    = (const float*)d_in[0];
    const float* n1g  = (const float*)d_in[1];
    const float* n1b  = (const float*)d_in[2];
    const float* qkvw = (const float*)d_in[3];
    const float* qkvb = (const float*)d_in[4];
    const float* pw   = (const float*)d_in[5];
    const float* pb   = (const float*)d_in[6];
    const float* tab  = (const float*)d_in[7];
    const float* n2g  = (const float*)d_in[8];
    const float* n2b  = (const float*)d_in[9];
    const float* f1w  = (const float*)d_in[10];
    const float* f1b  = (const float*)d_in[11];
    const float* f2w  = (const float*)d_in[12];
    const float* f2b  = (const float*)d_in[13];
    const int*   ridx = (const int*)  d_in[14];

    bf16 *p_xwb, *p_qkvb, *p_attb, *p_xn2b, *p_hb, *p_wqkv, *p_wp, *p_wf1, *p_wf2;
    float *p_x2, *p_bias6;
    cudaGetSymbolAddress((void**)&p_xwb,  g_xwb);
    cudaGetSymbolAddress((void**)&p_qkvb, g_qkvb);
    cudaGetSymbolAddress((void**)&p_attb, g_attb);
    cudaGetSymbolAddress((void**)&p_x2,   g_x2);
    cudaGetSymbolAddress((void**)&p_xn2b, g_xn2b);
    cudaGetSymbolAddress((void**)&p_hb,   g_hb);
    cudaGetSymbolAddress((void**)&p_wqkv, g_wqkv);
    cudaGetSymbolAddress((void**)&p_wp,   g_wp);
    cudaGetSymbolAddress((void**)&p_wf1,  g_wf1);
    cudaGetSymbolAddress((void**)&p_wf2,  g_wf2);
    cudaGetSymbolAddress((void**)&p_bias6, g_bias6);

    // 0. weights -> bf16, bias table -> dense
    prep_kernel<<<(N_WTOT + N_BIAS + 255) / 256, 256>>>(qkvw, pw, f1w, f2w, tab, ridx);
    // 1. LN1 + shift + window partition
    ln_warp<true><<<TOK / 8, 256>>>(x, n1g, n1b, p_xwb);
    // 2. QKV GEMM -> bf16
    gemm_bf16<0, bf16><<<dim3(576 / BN, TOK / BM), 256>>>(p_xwb, p_wqkv, qkvb, nullptr, p_qkvb, TOK, 576, CD);
    // 3. attention (tensor cores)
    attn_mma<<<dim3(3, NWIN), 256>>>(p_qkvb, p_bias6, p_attb);
    // 4. proj GEMM + reverse/unshift scatter + residual(x)
    gemm_bf16<3, float><<<dim3(CD / BN, TOK / BM), 256>>>(p_attb, p_wp, pb, x, p_x2, TOK, CD, CD);
    // 5. LN2
    ln_warp<false><<<TOK / 8, 256>>>(p_x2, n2g, n2b, p_xn2b);
    // 6. FC1 + GELU
    gemm_bf16<1, bf16><<<dim3(HID / BN, TOK / BM), 256>>>(p_xn2b, p_wf1, f1b, nullptr, p_hb, TOK, HID, CD);
    // 7. FC2 + residual(x2) -> d_out
    gemm_bf16<2, float><<<dim3(CD / BN, TOK / BM), 256>>>(p_hb, p_wf2, f2b, p_x2, (float*)d_out, TOK, CD, HID);
}